// round 16
// baseline (speedup 1.0000x reference)
#include <cuda_runtime.h>
#include <math.h>

#define T_    1024
#define NKV_  4
#define DH_   64
#define NB_   63
#define PW_   256            // proj row width = NKV*DH
#define SCALE_ 0.125f

// ---------------- device scratch (no allocations allowed) ----------------
__device__ float g_proj[6][T_ * PW_];   // 0:kcmp 1:vcmp 2:kslc 3:vslc 4:kwin 5:vwin  [t][k*64+d]
__device__ float g_gates[T_ * 48];      // sigmoid gates [t][h*3+j]
__device__ float g_ksum[NB_ * PW_];     // [n][k*64+d]
__device__ float g_vsum[NB_ * PW_];
__device__ int   g_sel[NKV_ * T_ * 8];  // top-8 block ids per (k,t)

// ---------------- packed f32x2 helpers ----------------
__device__ __forceinline__ unsigned long long pk2(float lo, float hi) {
    unsigned long long r;
    asm("mov.b64 %0, {%1, %2};" : "=l"(r) : "f"(lo), "f"(hi));
    return r;
}
__device__ __forceinline__ float2 upk2(unsigned long long v) {
    float2 r;
    asm("mov.b64 {%0, %1}, %2;" : "=f"(r.x), "=f"(r.y) : "l"(v));
    return r;
}
__device__ __forceinline__ unsigned long long fma2(unsigned long long a,
                                                   unsigned long long b,
                                                   unsigned long long c) {
    unsigned long long d;
    asm("fma.rn.f32x2 %0, %1, %2, %3;" : "=l"(d) : "l"(a), "l"(b), "l"(c));
    return d;
}

// =====================================================================
// 1) projections: C[z] = x @ W[z]^T, M=1024 N=256 K=1024, 64x64 tiles
// =====================================================================
__global__ void proj_gemm(const float* __restrict__ x,
                          const float* __restrict__ w0, const float* __restrict__ w1,
                          const float* __restrict__ w2, const float* __restrict__ w3,
                          const float* __restrict__ w4, const float* __restrict__ w5)
{
    const float* W;
    switch (blockIdx.z) {
        case 0: W = w0; break; case 1: W = w1; break; case 2: W = w2; break;
        case 3: W = w3; break; case 4: W = w4; break; default: W = w5; break;
    }
    float* C = g_proj[blockIdx.z];

    __shared__ __align__(16) float As[16][68];
    __shared__ __align__(16) float Bs[16][68];

    int tx = threadIdx.x, ty = threadIdx.y;
    int tid = ty * 16 + tx;
    int lr = tid >> 2;
    int lk = (tid & 3) << 2;
    int row0 = blockIdx.y * 64;
    int col0 = blockIdx.x * 64;

    unsigned long long acc[4][2] = {{0ull,0ull},{0ull,0ull},{0ull,0ull},{0ull,0ull}};

    for (int kt = 0; kt < 1024; kt += 16) {
        float4 av = *(const float4*)(x + (size_t)(row0 + lr) * 1024 + kt + lk);
        float4 wv = *(const float4*)(W + (size_t)(col0 + lr) * 1024 + kt + lk);
        As[lk + 0][lr] = av.x; As[lk + 1][lr] = av.y; As[lk + 2][lr] = av.z; As[lk + 3][lr] = av.w;
        Bs[lk + 0][lr] = wv.x; Bs[lk + 1][lr] = wv.y; Bs[lk + 2][lr] = wv.z; Bs[lk + 3][lr] = wv.w;
        __syncthreads();
        #pragma unroll
        for (int kk = 0; kk < 16; kk++) {
            float4 a4 = *(const float4*)&As[kk][ty * 4];
            unsigned long long bp0 = *(const unsigned long long*)&Bs[kk][tx * 4];
            unsigned long long bp1 = *(const unsigned long long*)&Bs[kk][tx * 4 + 2];
            unsigned long long a0 = pk2(a4.x, a4.x);
            unsigned long long a1 = pk2(a4.y, a4.y);
            unsigned long long a2 = pk2(a4.z, a4.z);
            unsigned long long a3 = pk2(a4.w, a4.w);
            acc[0][0] = fma2(a0, bp0, acc[0][0]); acc[0][1] = fma2(a0, bp1, acc[0][1]);
            acc[1][0] = fma2(a1, bp0, acc[1][0]); acc[1][1] = fma2(a1, bp1, acc[1][1]);
            acc[2][0] = fma2(a2, bp0, acc[2][0]); acc[2][1] = fma2(a2, bp1, acc[2][1]);
            acc[3][0] = fma2(a3, bp0, acc[3][0]); acc[3][1] = fma2(a3, bp1, acc[3][1]);
        }
        __syncthreads();
    }
    #pragma unroll
    for (int i = 0; i < 4; i++) {
        float2 c0 = upk2(acc[i][0]);
        float2 c1 = upk2(acc[i][1]);
        int r = row0 + ty * 4 + i;
        int c = col0 + tx * 4;
        *(float4*)(C + (size_t)r * PW_ + c) = make_float4(c0.x, c0.y, c1.x, c1.y);
    }
}

// =====================================================================
// 2) gates: sigmoid(x @ gate_w^T + gate_b), N=48
// =====================================================================
__global__ void gate_gemm(const float* __restrict__ x,
                          const float* __restrict__ gw,
                          const float* __restrict__ gb)
{
    __shared__ __align__(16) float As[16][68];
    __shared__ __align__(16) float Bs[16][68];

    int tx = threadIdx.x, ty = threadIdx.y;
    int tid = ty * 16 + tx;
    int lr = tid >> 2;
    int lk = (tid & 3) << 2;
    int row0 = blockIdx.y * 64;

    float acc[4][4] = {};

    for (int kt = 0; kt < 1024; kt += 16) {
        float4 av = *(const float4*)(x + (size_t)(row0 + lr) * 1024 + kt + lk);
        float4 wv = make_float4(0.f, 0.f, 0.f, 0.f);
        if (lr < 48) wv = *(const float4*)(gw + (size_t)lr * 1024 + kt + lk);
        As[lk + 0][lr] = av.x; As[lk + 1][lr] = av.y; As[lk + 2][lr] = av.z; As[lk + 3][lr] = av.w;
        Bs[lk + 0][lr] = wv.x; Bs[lk + 1][lr] = wv.y; Bs[lk + 2][lr] = wv.z; Bs[lk + 3][lr] = wv.w;
        __syncthreads();
        #pragma unroll
        for (int kk = 0; kk < 16; kk++) {
            float a[4], b[4];
            #pragma unroll
            for (int i = 0; i < 4; i++) a[i] = As[kk][ty * 4 + i];
            #pragma unroll
            for (int j = 0; j < 4; j++) b[j] = Bs[kk][tx * 4 + j];
            #pragma unroll
            for (int i = 0; i < 4; i++)
                #pragma unroll
                for (int j = 0; j < 4; j++) acc[i][j] = fmaf(a[i], b[j], acc[i][j]);
        }
        __syncthreads();
    }
    #pragma unroll
    for (int i = 0; i < 4; i++) {
        int r = row0 + ty * 4 + i;
        #pragma unroll
        for (int j = 0; j < 4; j++) {
            int c = tx * 4 + j;
            if (c < 48) {
                float v = acc[i][j] + gb[c];
                g_gates[r * 48 + c] = 1.f / (1.f + expf(-v));
            }
        }
    }
}

// =====================================================================
// 3) compressed block summaries: 2048 -> GELU(erf) -> 64 -> 64
//    grid (63, 4, 2): z=0 keys, z=1 values. 64 threads.
// =====================================================================
__global__ void summarize_kernel(const float* __restrict__ bpos,
    const float* __restrict__ ck1w, const float* __restrict__ ck1b,
    const float* __restrict__ ck2w, const float* __restrict__ ck2b,
    const float* __restrict__ cv1w, const float* __restrict__ cv1b,
    const float* __restrict__ cv2w, const float* __restrict__ cv2b)
{
    int n = blockIdx.x, k = blockIdx.y, z = blockIdx.z;
    const float* inp = z ? g_proj[1] : g_proj[0];
    const float* w1  = z ? cv1w : ck1w;
    const float* b1  = z ? cv1b : ck1b;
    const float* w2  = z ? cv2w : ck2w;
    const float* b2  = z ? cv2b : ck2b;
    float* outp      = z ? g_vsum : g_ksum;

    __shared__ __align__(16) float flat[2048];
    __shared__ float h1[64];
    int tid = threadIdx.x;
    int start = 16 * n;

    for (int j = tid; j < 2048; j += 64) {
        int c = j >> 6, d = j & 63;
        flat[j] = inp[(size_t)(start + c) * PW_ + k * DH_ + d] + bpos[j];
    }
    __syncthreads();

    const float4* wr = (const float4*)(w1 + (size_t)tid * 2048);
    const float4* fl = (const float4*)flat;
    float a0 = 0.f, a1 = 0.f, a2 = 0.f, a3 = 0.f;
    #pragma unroll 4
    for (int jj = 0; jj < 512; jj++) {
        float4 f = fl[jj];
        float4 wv = __ldg(&wr[jj]);
        a0 = fmaf(f.x, wv.x, a0);
        a1 = fmaf(f.y, wv.y, a1);
        a2 = fmaf(f.z, wv.z, a2);
        a3 = fmaf(f.w, wv.w, a3);
    }
    float acc = b1[tid] + ((a0 + a2) + (a1 + a3));
    h1[tid] = 0.5f * acc * (1.f + erff(acc * 0.70710678118654752440f));
    __syncthreads();

    float acc2 = b2[tid];
    const float* w2r = w2 + (size_t)tid * 64;
    #pragma unroll
    for (int j = 0; j < 64; j++) acc2 = fmaf(h1[j], __ldg(w2r + j), acc2);
    outp[n * PW_ + k * DH_ + tid] = acc2;
}

// =====================================================================
// 4) compressed attention + top-8 selection. grid (128, 4), 256 thr.
//    Warp w handles t = blockIdx.x*8 + w. Initializes d_out = g0*out_cmp.
// =====================================================================
__global__ void cmp_kernel(const float* __restrict__ q, float* __restrict__ out)
{
    __shared__ __align__(16) float ks[64 * 65];
    __shared__ __align__(16) float vs[64 * 65];
    __shared__ float ps[8][4 * NB_];

    int k = blockIdx.y, tid = threadIdx.x;

    for (int i = tid; i < 64 * 64; i += 256) {
        int n = i >> 6, d = i & 63;
        float kv = 0.f, vv = 0.f;
        if (n < NB_) {
            kv = g_ksum[n * PW_ + k * DH_ + d];
            vv = g_vsum[n * PW_ + k * DH_ + d];
        }
        ks[n * 65 + d] = kv;
        vs[n * 65 + d] = vv;
    }
    __syncthreads();

    int w = tid >> 5, lane = tid & 31;
    int t = blockIdx.x * 8 + w;
    int n0 = lane, n1 = lane + 32;
    bool has1 = (n1 < NB_);
    int nvis = (t >= 31) ? (((t - 31) >> 4) + 1) : 0;

    // scores: 4 heads x 2 blocks per lane
    float s0a[4] = {0,0,0,0}, s1a[4] = {0,0,0,0};
    for (int d = 0; d < 64; d++) {
        float k0 = ks[n0 * 65 + d];
        float k1 = ks[n1 * 65 + d];   // row 63 zero-padded
        #pragma unroll
        for (int r = 0; r < 4; r++) {
            float qd = __ldg(q + (((size_t)(r * 4 + k) * T_ + t) << 6) + d);
            s0a[r] = fmaf(qd, k0, s0a[r]);
            s1a[r] = fmaf(qd, k1, s1a[r]);
        }
    }

    float p0[4], p1[4];
    #pragma unroll
    for (int r = 0; r < 4; r++) {
        float sc0 = (n0 < nvis) ? s0a[r] * SCALE_ : -1e30f;
        float sc1 = has1 ? ((n1 < nvis) ? s1a[r] * SCALE_ : -1e30f)
                         : -__int_as_float(0x7f800000);  // -inf for nonexistent block
        float m = fmaxf(sc0, sc1);
        for (int o = 16; o; o >>= 1) m = fmaxf(m, __shfl_xor_sync(0xffffffffu, m, o));
        float e0 = expf(sc0 - m);
        float e1 = expf(sc1 - m);
        float sum = e0 + e1;
        for (int o = 16; o; o >>= 1) sum += __shfl_xor_sync(0xffffffffu, sum, o);
        float inv = 1.f / sum;
        p0[r] = e0 * inv; p1[r] = e1 * inv;
        ps[w][r * NB_ + n0] = p0[r];
        if (has1) ps[w][r * NB_ + n1] = p1[r];
    }
    __syncwarp();

    // top-8 of importance (sum over GQA group), ties -> lowest index
    float imp0 = p0[0] + p0[1] + p0[2] + p0[3];
    float imp1 = has1 ? (p1[0] + p1[1] + p1[2] + p1[3]) : -2.f;
    int selbase = (k * T_ + t) * 8;
    #pragma unroll
    for (int it = 0; it < 8; it++) {
        float bv; int bi;
        if (imp0 >= imp1) { bv = imp0; bi = n0; } else { bv = imp1; bi = n1; }
        for (int o = 16; o; o >>= 1) {
            float ov = __shfl_xor_sync(0xffffffffu, bv, o);
            int   oi = __shfl_xor_sync(0xffffffffu, bi, o);
            if (ov > bv || (ov == bv && oi < bi)) { bv = ov; bi = oi; }
        }
        if (lane == 0) g_sel[selbase + it] = bi;
        if (bi == n0) imp0 = -2.f;
        if (bi == n1) imp1 = -2.f;
    }

    // out_cmp (zero when nvis==0, matching vis.any mask), write g0*out_cmp
    int d0 = lane, d1 = lane + 32;
    float o0[4] = {0,0,0,0}, o1[4] = {0,0,0,0};
    for (int n = 0; n < nvis; n++) {
        float v0 = vs[n * 65 + d0], v1 = vs[n * 65 + d1];
        #pragma unroll
        for (int r = 0; r < 4; r++) {
            float p = ps[w][r * NB_ + n];
            o0[r] = fmaf(p, v0, o0[r]);
            o1[r] = fmaf(p, v1, o1[r]);
        }
    }
    #pragma unroll
    for (int r = 0; r < 4; r++) {
        int h = r * 4 + k;
        float g0 = g_gates[t * 48 + h * 3];
        size_t base = ((size_t)h * T_ + t) << 6;
        out[base + d0] = g0 * o0[r];
        out[base + d1] = g0 * o1[r];
    }
}

// =====================================================================
// 5) gathered attention over exactly 256 key rows per (k,t).
//    mode 0: top-8 blocks x 32 (selected branch, gate1)
//    mode 1: sliding window of 256 (gate2)
//    grid (1024, 4), 256 threads, 72KB dynamic smem.
// =====================================================================
__global__ void gather_attn(const float* __restrict__ q, float* __restrict__ out, int mode)
{
    extern __shared__ __align__(16) float sm[];
    float* kvS  = sm;                    // 256*65 = 16640
    float* qS   = sm + 16640;            // 256
    float* pS   = sm + 16896;            // 1024
    float* redS = sm + 17920;            // 64
    int*   posS = (int*)(sm + 17984);    // 256

    int t = blockIdx.x, k = blockIdx.y;
    int tid = threadIdx.x;
    int w = tid >> 5, lane = tid & 31;

    { // q for 4 GQA heads
        int r = tid >> 6, d = tid & 63;
        qS[tid] = q[(((size_t)(r * 4 + k) * T_ + t) << 6) + d];
    }

    int pos;
    if (mode == 0) {
        int blk = g_sel[(k * T_ + t) * 8 + (tid >> 5)];
        pos = blk * 16 + (tid & 31);
    } else {
        int j0 = t - 255; if (j0 < 0) j0 = 0;
        pos = j0 + tid;
    }
    bool valid = (pos <= t);   // pos < T always for both modes
    posS[tid] = pos;
    __syncthreads();

    const float* K = (mode == 0) ? g_proj[2] : g_proj[4];
    const float* V = (mode == 0) ? g_proj[3] : g_proj[5];

    for (int i = tid; i < 16384; i += 256) {
        int row = i >> 6, d = i & 63;
        kvS[row * 65 + d] = K[(size_t)posS[row] * PW_ + k * DH_ + d];
    }
    __syncthreads();

    // scores
    float sc[4] = {0,0,0,0};
    {
        int s = tid;
        #pragma unroll 8
        for (int d = 0; d < 64; d++) {
            float kd = kvS[s * 65 + d];
            sc[0] = fmaf(kd, qS[d],       sc[0]);
            sc[1] = fmaf(kd, qS[64 + d],  sc[1]);
            sc[2] = fmaf(kd, qS[128 + d], sc[2]);
            sc[3] = fmaf(kd, qS[192 + d], sc[3]);
        }
    }
    #pragma unroll
    for (int r = 0; r < 4; r++) sc[r] = valid ? sc[r] * SCALE_ : -1e30f;

    // block softmax over 256 positions, per head
    #pragma unroll
    for (int r = 0; r < 4; r++) {
        float v = sc[r];
        for (int o = 16; o; o >>= 1) v = fmaxf(v, __shfl_xor_sync(0xffffffffu, v, o));
        if (lane == 0) redS[w * 4 + r] = v;
    }
    __syncthreads();
    float m[4];
    #pragma unroll
    for (int r = 0; r < 4; r++) {
        float v = redS[r];
        #pragma unroll
        for (int ww = 1; ww < 8; ww++) v = fmaxf(v, redS[ww * 4 + r]);
        m[r] = v;
    }
    float e[4];
    #pragma unroll
    for (int r = 0; r < 4; r++) {
        e[r] = expf(sc[r] - m[r]);
        float v = e[r];
        for (int o = 16; o; o >>= 1) v += __shfl_xor_sync(0xffffffffu, v, o);
        if (lane == 0) redS[32 + w * 4 + r] = v;
    }
    __syncthreads();
    #pragma unroll
    for (int r = 0; r < 4; r++) {
        float v = 0.f;
        #pragma unroll
        for (int ww = 0; ww < 8; ww++) v += redS[32 + ww * 4 + r];
        pS[tid * 4 + r] = e[r] / v;
    }
    __syncthreads();

    // V tile (overwrite kvS)
    for (int i = tid; i < 16384; i += 256) {
        int row = i >> 6, d = i & 63;
        kvS[row * 65 + d] = V[(size_t)posS[row] * PW_ + k * DH_ + d];
    }
    __syncthreads();

    // output accumulation: thread per (r, d)
    {
        int r = tid >> 6, d = tid & 63;
        float a0 = 0.f, a1 = 0.f, a2 = 0.f, a3 = 0.f;
        #pragma unroll 4
        for (int s = 0; s < 256; s += 4) {
            a0 = fmaf(pS[(s + 0) * 4 + r], kvS[(s + 0) * 65 + d], a0);
            a1 = fmaf(pS[(s + 1) * 4 + r], kvS[(s + 1) * 65 + d], a1);
            a2 = fmaf(pS[(s + 2) * 4 + r], kvS[(s + 2) * 65 + d], a2);
            a3 = fmaf(pS[(s + 3) * 4 + r], kvS[(s + 3) * 65 + d], a3);
        }
        float acc = (a0 + a1) + (a2 + a3);
        int h = r * 4 + k;
        float g = g_gates[t * 48 + h * 3 + ((mode == 0) ? 1 : 2)];
        size_t idx = (((size_t)h * T_ + t) << 6) + d;
        out[idx] += g * acc;
    }
}

// =====================================================================
extern "C" void kernel_launch(void* const* d_in, const int* in_sizes, int n_in,
                              void* d_out, int out_size)
{
    const float* x      = (const float*)d_in[0];
    const float* q      = (const float*)d_in[1];
    const float* gate_w = (const float*)d_in[2];
    const float* gate_b = (const float*)d_in[3];
    const float* wk_cmp = (const float*)d_in[4];
    const float* wv_cmp = (const float*)d_in[5];
    const float* wk_slc = (const float*)d_in[6];
    const float* wv_slc = (const float*)d_in[7];
    const float* wk_win = (const float*)d_in[8];
    const float* wv_win = (const float*)d_in[9];
    const float* bpos   = (const float*)d_in[10];
    const float* ck1w   = (const float*)d_in[11];
    const float* ck1b   = (const float*)d_in[12];
    const float* ck2w   = (const float*)d_in[13];
    const float* ck2b   = (const float*)d_in[14];
    const float* cv1w   = (const float*)d_in[15];
    const float* cv1b   = (const float*)d_in[16];
    const float* cv2w   = (const float*)d_in[17];
    const float* cv2b   = (const float*)d_in[18];
    float* out = (float*)d_out;

    const int GATHER_SMEM = (17984 + 256) * 4;  // 72,960 bytes
    cudaFuncSetAttribute(gather_attn, cudaFuncAttributeMaxDynamicSharedMemorySize, GATHER_SMEM);

    proj_gemm<<<dim3(4, 16, 6), dim3(16, 16)>>>(x, wk_cmp, wv_cmp, wk_slc, wv_slc, wk_win, wv_win);
    gate_gemm<<<dim3(1, 16), dim3(16, 16)>>>(x, gate_w, gate_b);
    summarize_kernel<<<dim3(63, 4, 2), 64>>>(bpos, ck1w, ck1b, ck2w, ck2b, cv1w, cv1b, cv2w, cv2b);
    cmp_kernel<<<dim3(128, 4), 256>>>(q, out);
    gather_attn<<<dim3(1024, 4), 256, GATHER_SMEM>>>(q, out, 0);
    gather_attn<<<dim3(1024, 4), 256, GATHER_SMEM>>>(q, out, 1);
}

// round 17
// speedup vs baseline: 1.7297x; 1.7297x over previous
#include <cuda_runtime.h>
#include <math.h>

#define T_    1024
#define DH_   64
#define NB_   63
#define PW_   256
#define SCALE_ 0.125f

typedef unsigned long long ull;

// ---------------- device scratch ----------------
__device__ float g_proj[6][T_ * PW_];   // 0:kcmp 1:vcmp 2:kslc 3:vslc 4:kwin 5:vwin
__device__ float g_gates[T_ * 48];
__device__ float g_ksum[NB_ * PW_];
__device__ float g_vsum[NB_ * PW_];
__device__ int   g_sel[4 * T_ * 8];

// ---------------- packed f32x2 helpers ----------------
__device__ __forceinline__ ull pk2(float lo, float hi) {
    ull r; asm("mov.b64 %0, {%1, %2};" : "=l"(r) : "f"(lo), "f"(hi)); return r;
}
__device__ __forceinline__ float2 upk2(ull v) {
    float2 r; asm("mov.b64 {%0, %1}, %2;" : "=f"(r.x), "=f"(r.y) : "l"(v)); return r;
}
__device__ __forceinline__ ull fma2(ull a, ull b, ull c) {
    ull d; asm("fma.rn.f32x2 %0, %1, %2, %3;" : "=l"(d) : "l"(a), "l"(b), "l"(c)); return d;
}

// =====================================================================
// 1) projections + gates: z<6 -> g_proj[z] = x @ W[z]^T  (1024x256x1024)
//    z==6 -> g_gates = sigmoid(x @ gate_w^T + gate_b)  (1024x48x1024)
//    128x64 tile, 8x4 microtile, fma.rn.f32x2
// =====================================================================
__global__ __launch_bounds__(256) void proj_gemm(
    const float* __restrict__ x,
    const float* __restrict__ w0, const float* __restrict__ w1,
    const float* __restrict__ w2, const float* __restrict__ w3,
    const float* __restrict__ w4, const float* __restrict__ w5,
    const float* __restrict__ gw, const float* __restrict__ gb)
{
    int z = blockIdx.z;
    bool is_gate = (z == 6);
    if (is_gate && blockIdx.x != 0) return;
    const float* W;
    switch (z) {
        case 0: W = w0; break; case 1: W = w1; break; case 2: W = w2; break;
        case 3: W = w3; break; case 4: W = w4; break; case 5: W = w5; break;
        default: W = gw; break;
    }

    __shared__ __align__(16) float As[16][132];
    __shared__ __align__(16) float Bs[16][68];

    int tx = threadIdx.x, ty = threadIdx.y;
    int tid = ty * 16 + tx;
    int rA0 = tid >> 2;              // 0..63
    int rA1 = rA0 + 64;              // 64..127
    int lk  = (tid & 3) << 2;
    int row0 = blockIdx.y * 128;
    int col0 = blockIdx.x * 64;

    ull acc[8][2];
    #pragma unroll
    for (int i = 0; i < 8; i++) { acc[i][0] = 0ull; acc[i][1] = 0ull; }

    for (int kt = 0; kt < 1024; kt += 16) {
        float4 a0 = *(const float4*)(x + (size_t)(row0 + rA0) * 1024 + kt + lk);
        float4 a1 = *(const float4*)(x + (size_t)(row0 + rA1) * 1024 + kt + lk);
        float4 wv = make_float4(0.f, 0.f, 0.f, 0.f);
        int wr = col0 + rA0;
        if (!is_gate || wr < 48) wv = *(const float4*)(W + (size_t)wr * 1024 + kt + lk);
        As[lk + 0][rA0] = a0.x; As[lk + 1][rA0] = a0.y; As[lk + 2][rA0] = a0.z; As[lk + 3][rA0] = a0.w;
        As[lk + 0][rA1] = a1.x; As[lk + 1][rA1] = a1.y; As[lk + 2][rA1] = a1.z; As[lk + 3][rA1] = a1.w;
        Bs[lk + 0][rA0] = wv.x; Bs[lk + 1][rA0] = wv.y; Bs[lk + 2][rA0] = wv.z; Bs[lk + 3][rA0] = wv.w;
        __syncthreads();
        #pragma unroll
        for (int kk = 0; kk < 16; kk++) {
            float4 av0 = *(const float4*)&As[kk][ty * 8];
            float4 av1 = *(const float4*)&As[kk][ty * 8 + 4];
            longlong2 bb = *(const longlong2*)&Bs[kk][tx * 4];
            ull b0 = (ull)bb.x, b1 = (ull)bb.y;
            ull ap;
            ap = pk2(av0.x, av0.x); acc[0][0] = fma2(ap, b0, acc[0][0]); acc[0][1] = fma2(ap, b1, acc[0][1]);
            ap = pk2(av0.y, av0.y); acc[1][0] = fma2(ap, b0, acc[1][0]); acc[1][1] = fma2(ap, b1, acc[1][1]);
            ap = pk2(av0.z, av0.z); acc[2][0] = fma2(ap, b0, acc[2][0]); acc[2][1] = fma2(ap, b1, acc[2][1]);
            ap = pk2(av0.w, av0.w); acc[3][0] = fma2(ap, b0, acc[3][0]); acc[3][1] = fma2(ap, b1, acc[3][1]);
            ap = pk2(av1.x, av1.x); acc[4][0] = fma2(ap, b0, acc[4][0]); acc[4][1] = fma2(ap, b1, acc[4][1]);
            ap = pk2(av1.y, av1.y); acc[5][0] = fma2(ap, b0, acc[5][0]); acc[5][1] = fma2(ap, b1, acc[5][1]);
            ap = pk2(av1.z, av1.z); acc[6][0] = fma2(ap, b0, acc[6][0]); acc[6][1] = fma2(ap, b1, acc[6][1]);
            ap = pk2(av1.w, av1.w); acc[7][0] = fma2(ap, b0, acc[7][0]); acc[7][1] = fma2(ap, b1, acc[7][1]);
        }
        __syncthreads();
    }

    if (!is_gate) {
        float* C = g_proj[z];
        #pragma unroll
        for (int i = 0; i < 8; i++) {
            float2 c0 = upk2(acc[i][0]);
            float2 c1 = upk2(acc[i][1]);
            int r = row0 + ty * 8 + i;
            int c = col0 + tx * 4;
            *(float4*)(C + (size_t)r * PW_ + c) = make_float4(c0.x, c0.y, c1.x, c1.y);
        }
    } else {
        #pragma unroll
        for (int i = 0; i < 8; i++) {
            float2 c0 = upk2(acc[i][0]);
            float2 c1 = upk2(acc[i][1]);
            int r = row0 + ty * 8 + i;
            int c = tx * 4;
            float v[4] = {c0.x, c0.y, c1.x, c1.y};
            #pragma unroll
            for (int jj = 0; jj < 4; jj++) {
                int cc = c + jj;
                if (cc < 48) {
                    float t2 = v[jj] + gb[cc];
                    g_gates[r * 48 + cc] = 1.f / (1.f + expf(-t2));
                }
            }
        }
    }
}

// =====================================================================
// 3) compressed block summaries (unchanged from passing R15)
// =====================================================================
__global__ void summarize_kernel(const float* __restrict__ bpos,
    const float* __restrict__ ck1w, const float* __restrict__ ck1b,
    const float* __restrict__ ck2w, const float* __restrict__ ck2b,
    const float* __restrict__ cv1w, const float* __restrict__ cv1b,
    const float* __restrict__ cv2w, const float* __restrict__ cv2b)
{
    int n = blockIdx.x, k = blockIdx.y, z = blockIdx.z;
    const float* inp = z ? g_proj[1] : g_proj[0];
    const float* w1  = z ? cv1w : ck1w;
    const float* b1  = z ? cv1b : ck1b;
    const float* w2  = z ? cv2w : ck2w;
    const float* b2  = z ? cv2b : ck2b;
    float* outp      = z ? g_vsum : g_ksum;

    __shared__ __align__(16) float flat[2048];
    __shared__ float h1[64];
    int tid = threadIdx.x;
    int start = 16 * n;

    for (int j = tid; j < 2048; j += 64) {
        int c = j >> 6, d = j & 63;
        flat[j] = inp[(size_t)(start + c) * PW_ + k * DH_ + d] + bpos[j];
    }
    __syncthreads();

    const float4* wr = (const float4*)(w1 + (size_t)tid * 2048);
    const float4* fl = (const float4*)flat;
    float a0 = 0.f, a1 = 0.f, a2 = 0.f, a3 = 0.f;
    #pragma unroll 4
    for (int jj = 0; jj < 512; jj++) {
        float4 f = fl[jj];
        float4 wv = __ldg(&wr[jj]);
        a0 = fmaf(f.x, wv.x, a0);
        a1 = fmaf(f.y, wv.y, a1);
        a2 = fmaf(f.z, wv.z, a2);
        a3 = fmaf(f.w, wv.w, a3);
    }
    float acc = b1[tid] + ((a0 + a2) + (a1 + a3));
    h1[tid] = 0.5f * acc * (1.f + erff(acc * 0.70710678118654752440f));
    __syncthreads();

    float acc2 = b2[tid];
    const float* w2r = w2 + (size_t)tid * 64;
    #pragma unroll
    for (int j = 0; j < 64; j++) acc2 = fmaf(h1[j], __ldg(w2r + j), acc2);
    outp[n * PW_ + k * DH_ + tid] = acc2;
}

// =====================================================================
// 4) compressed attention + top-8 selection (unchanged from passing R15)
// =====================================================================
__global__ void cmp_kernel(const float* __restrict__ q, float* __restrict__ out)
{
    __shared__ __align__(16) float ks[64 * 65];
    __shared__ __align__(16) float vs[64 * 65];
    __shared__ float ps[8][4 * NB_];

    int k = blockIdx.y, tid = threadIdx.x;

    for (int i = tid; i < 64 * 64; i += 256) {
        int n = i >> 6, d = i & 63;
        float kv = 0.f, vv = 0.f;
        if (n < NB_) {
            kv = g_ksum[n * PW_ + k * DH_ + d];
            vv = g_vsum[n * PW_ + k * DH_ + d];
        }
        ks[n * 65 + d] = kv;
        vs[n * 65 + d] = vv;
    }
    __syncthreads();

    int w = tid >> 5, lane = tid & 31;
    int t = blockIdx.x * 8 + w;
    int n0 = lane, n1 = lane + 32;
    bool has1 = (n1 < NB_);
    int nvis = (t >= 31) ? (((t - 31) >> 4) + 1) : 0;

    float s0a[4] = {0,0,0,0}, s1a[4] = {0,0,0,0};
    for (int d = 0; d < 64; d++) {
        float k0 = ks[n0 * 65 + d];
        float k1 = ks[n1 * 65 + d];
        #pragma unroll
        for (int r = 0; r < 4; r++) {
            float qd = __ldg(q + (((size_t)(r * 4 + k) * T_ + t) << 6) + d);
            s0a[r] = fmaf(qd, k0, s0a[r]);
            s1a[r] = fmaf(qd, k1, s1a[r]);
        }
    }

    float p0[4], p1[4];
    #pragma unroll
    for (int r = 0; r < 4; r++) {
        float sc0 = (n0 < nvis) ? s0a[r] * SCALE_ : -1e30f;
        float sc1 = has1 ? ((n1 < nvis) ? s1a[r] * SCALE_ : -1e30f)
                         : -__int_as_float(0x7f800000);
        float m = fmaxf(sc0, sc1);
        for (int o = 16; o; o >>= 1) m = fmaxf(m, __shfl_xor_sync(0xffffffffu, m, o));
        float e0 = expf(sc0 - m);
        float e1 = expf(sc1 - m);
        float sum = e0 + e1;
        for (int o = 16; o; o >>= 1) sum += __shfl_xor_sync(0xffffffffu, sum, o);
        float inv = 1.f / sum;
        p0[r] = e0 * inv; p1[r] = e1 * inv;
        ps[w][r * NB_ + n0] = p0[r];
        if (has1) ps[w][r * NB_ + n1] = p1[r];
    }
    __syncwarp();

    float imp0 = p0[0] + p0[1] + p0[2] + p0[3];
    float imp1 = has1 ? (p1[0] + p1[1] + p1[2] + p1[3]) : -2.f;
    int selbase = (k * T_ + t) * 8;
    #pragma unroll
    for (int it = 0; it < 8; it++) {
        float bv; int bi;
        if (imp0 >= imp1) { bv = imp0; bi = n0; } else { bv = imp1; bi = n1; }
        for (int o = 16; o; o >>= 1) {
            float ov = __shfl_xor_sync(0xffffffffu, bv, o);
            int   oi = __shfl_xor_sync(0xffffffffu, bi, o);
            if (ov > bv || (ov == bv && oi < bi)) { bv = ov; bi = oi; }
        }
        if (lane == 0) g_sel[selbase + it] = bi;
        if (bi == n0) imp0 = -2.f;
        if (bi == n1) imp1 = -2.f;
    }

    int d0 = lane, d1 = lane + 32;
    float o0[4] = {0,0,0,0}, o1[4] = {0,0,0,0};
    for (int n = 0; n < nvis; n++) {
        float v0 = vs[n * 65 + d0], v1 = vs[n * 65 + d1];
        #pragma unroll
        for (int r = 0; r < 4; r++) {
            float p = ps[w][r * NB_ + n];
            o0[r] = fmaf(p, v0, o0[r]);
            o1[r] = fmaf(p, v1, o1[r]);
        }
    }
    #pragma unroll
    for (int r = 0; r < 4; r++) {
        int h = r * 4 + k;
        float g0 = g_gates[t * 48 + h * 3];
        size_t base = ((size_t)h * T_ + t) << 6;
        out[base + d0] = g0 * o0[r];
        out[base + d1] = g0 * o1[r];
    }
}

// =====================================================================
// 5) gathered attention, fully vectorized float4 + XOR swizzle.
//    mode 0: top-8 blocks x 32 (gate1); mode 1: window 256 (gate2)
// =====================================================================
__global__ __launch_bounds__(256) void gather_attn(const float* __restrict__ q,
                                                   float* __restrict__ out, int mode)
{
    extern __shared__ __align__(16) float4 sm4[];
    float4* kv4  = sm4;                       // [0, 4096): row*16 + (j ^ (row&15))
    float4* q4   = sm4 + 4096;                // [4096, 4160)
    float*  pS   = (float*)(sm4 + 4160);      // 1024 floats
    float4* part = sm4 + 4416;                // 256 f4 (red overlays this)
    float*  red  = (float*)part;              // 64 floats (softmax phase only)
    int*    posS = (int*)(sm4 + 4672);        // 256 ints

    int t = blockIdx.x, k = blockIdx.y;
    int tid = threadIdx.x;
    int w = tid >> 5, lane = tid & 31;

    if (tid < 64) {
        int r = tid >> 4, j = tid & 15;
        q4[tid] = *(const float4*)(q + (((size_t)(r * 4 + k) * T_ + t) << 6) + j * 4);
    }

    int pos;
    if (mode == 0) {
        int blk = g_sel[(k * T_ + t) * 8 + w];
        pos = blk * 16 + lane;
    } else {
        int j0 = t - 255; if (j0 < 0) j0 = 0;
        pos = j0 + tid;
    }
    bool valid = (pos <= t);
    posS[tid] = pos;
    __syncthreads();

    const float4* K4 = (const float4*)((mode == 0) ? g_proj[2] : g_proj[4]);
    const float4* V4 = (const float4*)((mode == 0) ? g_proj[3] : g_proj[5]);

    #pragma unroll
    for (int i = 0; i < 16; i++) {
        int idx = tid + (i << 8);
        int row = idx >> 4, j = idx & 15;
        kv4[(row << 4) + (j ^ (row & 15))] = K4[(size_t)posS[row] * 64 + (k << 4) + j];
    }
    __syncthreads();

    // ---- scores (s = tid) ----
    int sw = tid & 15;
    float sc[4] = {0, 0, 0, 0};
    #pragma unroll
    for (int j = 0; j < 16; j++) {
        float4 kd = kv4[(tid << 4) + (j ^ sw)];
        #pragma unroll
        for (int r = 0; r < 4; r++) {
            float4 qv = q4[r * 16 + j];
            sc[r] = fmaf(kd.x, qv.x, sc[r]);
            sc[r] = fmaf(kd.y, qv.y, sc[r]);
            sc[r] = fmaf(kd.z, qv.z, sc[r]);
            sc[r] = fmaf(kd.w, qv.w, sc[r]);
        }
    }
    #pragma unroll
    for (int r = 0; r < 4; r++) sc[r] = valid ? sc[r] * SCALE_ : -1e30f;

    // ---- block softmax per head ----
    #pragma unroll
    for (int r = 0; r < 4; r++) {
        float v = sc[r];
        for (int o = 16; o; o >>= 1) v = fmaxf(v, __shfl_xor_sync(0xffffffffu, v, o));
        if (lane == 0) red[w * 4 + r] = v;
    }
    __syncthreads();
    float m[4];
    #pragma unroll
    for (int r = 0; r < 4; r++) {
        float v = red[r];
        #pragma unroll
        for (int ww = 1; ww < 8; ww++) v = fmaxf(v, red[ww * 4 + r]);
        m[r] = v;
    }
    float e[4];
    #pragma unroll
    for (int r = 0; r < 4; r++) {
        e[r] = expf(sc[r] - m[r]);
        float v = e[r];
        for (int o = 16; o; o >>= 1) v += __shfl_xor_sync(0xffffffffu, v, o);
        if (lane == 0) red[32 + w * 4 + r] = v;
    }
    __syncthreads();
    #pragma unroll
    for (int r = 0; r < 4; r++) {
        float v = 0.f;
        #pragma unroll
        for (int ww = 0; ww < 8; ww++) v += red[32 + ww * 4 + r];
        pS[r * 256 + tid] = e[r] / v;
    }

    // ---- V tile (kv4 reuse; all reads done, red done) ----
    #pragma unroll
    for (int i = 0; i < 16; i++) {
        int idx = tid + (i << 8);
        int row = idx >> 4, j = idx & 15;
        kv4[(row << 4) + (j ^ (row & 15))] = V4[(size_t)posS[row] * 64 + (k << 4) + j];
    }
    __syncthreads();

    // ---- output: warp = (head r, s-chunk), lane = (dq, sh) ----
    {
        int r = w & 3, chunk = w >> 2;
        int dq = lane & 15, sh = lane >> 4;
        int sb = chunk * 128 + sh * 64;
        float4 acc = make_float4(0.f, 0.f, 0.f, 0.f);
        #pragma unroll 4
        for (int i = 0; i < 64; i++) {
            int s2 = sb + i;
            float p = pS[r * 256 + s2];
            float4 v = kv4[(s2 << 4) + (dq ^ (s2 & 15))];
            acc.x = fmaf(p, v.x, acc.x);
            acc.y = fmaf(p, v.y, acc.y);
            acc.z = fmaf(p, v.z, acc.z);
            acc.w = fmaf(p, v.w, acc.w);
        }
        part[(w << 5) + lane] = acc;
    }
    __syncthreads();

    if (tid < 64) {
        int r = tid >> 4, dq = tid & 15;
        float4 a = part[((0 + r) << 5) + dq];
        float4 b = part[((0 + r) << 5) + 16 + dq];
        float4 c = part[((4 + r) << 5) + dq];
        float4 d = part[((4 + r) << 5) + 16 + dq];
        float4 s4 = make_float4((a.x + b.x) + (c.x + d.x),
                                (a.y + b.y) + (c.y + d.y),
                                (a.z + b.z) + (c.z + d.z),
                                (a.w + b.w) + (c.w + d.w));
        int h = r * 4 + k;
        float g = g_gates[t * 48 + h * 3 + ((mode == 0) ? 1 : 2)];
        float4* O = (float4*)out;
        size_t oi = (((size_t)h * T_ + t) << 4) + dq;
        float4 o = O[oi];
        o.x += g * s4.x; o.y += g * s4.y; o.z += g * s4.z; o.w += g * s4.w;
        O[oi] = o;
    }
}

// =====================================================================
extern "C" void kernel_launch(void* const* d_in, const int* in_sizes, int n_in,
                              void* d_out, int out_size)
{
    const float* x      = (const float*)d_in[0];
    const float* q      = (const float*)d_in[1];
    const float* gate_w = (const float*)d_in[2];
    const float* gate_b = (const float*)d_in[3];
    const float* wk_cmp = (const float*)d_in[4];
    const float* wv_cmp = (const float*)d_in[5];
    const float* wk_slc = (const float*)d_in[6];
    const float* wv_slc = (const float*)d_in[7];
    const float* wk_win = (const float*)d_in[8];
    const float* wv_win = (const float*)d_in[9];
    const float* bpos   = (const float*)d_in[10];
    const float* ck1w   = (const float*)d_in[11];
    const float* ck1b   = (const float*)d_in[12];
    const float* ck2w   = (const float*)d_in[13];
    const float* ck2b   = (const float*)d_in[14];
    const float* cv1w   = (const float*)d_in[15];
    const float* cv1b   = (const float*)d_in[16];
    const float* cv2w   = (const float*)d_in[17];
    const float* cv2b   = (const float*)d_in[18];
    float* out = (float*)d_out;

    const int GATHER_SMEM = 4736 * 16;  // 75,776 bytes
    cudaFuncSetAttribute(gather_attn, cudaFuncAttributeMaxDynamicSharedMemorySize, GATHER_SMEM);

    proj_gemm<<<dim3(4, 8, 7), dim3(16, 16)>>>(x, wk_cmp, wv_cmp, wk_slc, wv_slc,
                                               wk_win, wv_win, gate_w, gate_b);
    summarize_kernel<<<dim3(63, 4, 2), 64>>>(bpos, ck1w, ck1b, ck2w, ck2b, cv1w, cv1b, cv2w, cv2b);
    cmp_kernel<<<dim3(128, 4), 256>>>(q, out);
    gather_attn<<<dim3(1024, 4), 256, GATHER_SMEM>>>(q, out, 0);
    gather_attn<<<dim3(1024, 4), 256, GATHER_SMEM>>>(q, out, 1);
}